// round 2
// baseline (speedup 1.0000x reference)
#include <cuda_runtime.h>

#define BB 8
#define CC 256
#define HH 96
#define WW 96
#define HW (HH*WW)          // 9216
#define PATCH 21
#define NP    (PATCH*PATCH) // 441
#define HALFP 10
#define DILP 2

// Two channel-half partial sums of D = sum_c in1*in2.
// Each is B*H*W floats = 1.18 MB; both stay L2-resident for the gather.
__device__ float g_Dh[2][BB * HW];

// ---------------------------------------------------------------------------
// Kernel 1: channel dot product, split into two channel halves for occupancy.
// Block = 256 threads = 32 float4 lanes (128 spatial floats) x 8 groups of
// 16 channels. grid = (576, 2): blockIdx.y picks the channel half.
// 1152 blocks -> ~7.8 blocks/SM -> ~2000 threads/SM resident.
// ---------------------------------------------------------------------------
__global__ void __launch_bounds__(256) dot_kernel(const float* __restrict__ a,
                                                  const float* __restrict__ b) {
    __shared__ float4 red[256];

    const int tid  = threadIdx.x;
    const int lane = tid & 31;        // float4 spatial lane
    const int cg   = tid >> 5;        // channel group 0..7
    const int half = blockIdx.y;      // 0 or 1

    const int sbase = blockIdx.x * 128;        // spatial base in floats
    const int bidx  = sbase / HW;
    const int hw    = (sbase % HW) + lane * 4;

    const float4* __restrict__ A =
        (const float4*)(a + (size_t)bidx * CC * HW + hw);
    const float4* __restrict__ Bp =
        (const float4*)(b + (size_t)bidx * CC * HW + hw);

    const int cstride = HW / 4;                // 2304 float4 between channels
    const int c0 = half * 128 + cg * 16;

    float4 acc = make_float4(0.f, 0.f, 0.f, 0.f);
    #pragma unroll
    for (int c = 0; c < 16; ++c) {
        const size_t off = (size_t)(c0 + c) * cstride;
        float4 x = A[off];
        float4 y = Bp[off];
        acc.x = fmaf(x.x, y.x, acc.x);
        acc.y = fmaf(x.y, y.y, acc.y);
        acc.z = fmaf(x.z, y.z, acc.z);
        acc.w = fmaf(x.w, y.w, acc.w);
    }

    red[tid] = acc;
    __syncthreads();

    if (tid < 32) {
        float4 r = red[tid];
        #pragma unroll
        for (int k = 1; k < 8; ++k) {
            float4 t = red[tid + 32 * k];
            r.x += t.x; r.y += t.y; r.z += t.z; r.w += t.w;
        }
        ((float4*)g_Dh[half])[(size_t)blockIdx.x * 32 + tid] = r;
    }
}

// ---------------------------------------------------------------------------
// Kernel 2: gather / shift-replicate, summing the two channel halves.
// grid = (9, 441, 8): blockIdx.y = patch offset p, blockIdx.z = batch b.
// Per thread only one const-div-by-24 remains; py/px are block-uniform.
// One float4 store per thread; source reads are L2-resident.
// ---------------------------------------------------------------------------
__global__ void __launch_bounds__(256) gather_kernel(float* __restrict__ out) {
    const int tid = threadIdx.x;
    const int idx = blockIdx.x * 256 + tid;    // 0..2303 within the image
    const int p   = blockIdx.y;                // 0..440
    const int b   = blockIdx.z;                // 0..7

    const int y  = idx / 24;                   // const-div: mul-high
    const int x4 = idx - y * 24;

    const int py = p / PATCH;                  // block-uniform
    const int px = p - py * PATCH;

    const int sy    = y + (py - HALFP) * DILP;
    const int xbase = x4 * 4 + (px - HALFP) * DILP;   // even

    float4 v = make_float4(0.f, 0.f, 0.f, 0.f);

    if ((unsigned)sy < (unsigned)HH) {
        const int roff = (b * HH + sy) * WW;
        const float* __restrict__ r0 = g_Dh[0] + roff;
        const float* __restrict__ r1 = g_Dh[1] + roff;
        if (xbase >= 0 && xbase + 3 < WW) {
            float2 lo0 = *(const float2*)(r0 + xbase);
            float2 hi0 = *(const float2*)(r0 + xbase + 2);
            float2 lo1 = *(const float2*)(r1 + xbase);
            float2 hi1 = *(const float2*)(r1 + xbase + 2);
            v.x = lo0.x + lo1.x;
            v.y = lo0.y + lo1.y;
            v.z = hi0.x + hi1.x;
            v.w = hi0.y + hi1.y;
        } else {
            if ((unsigned)xbase       < (unsigned)WW) v.x = r0[xbase]     + r1[xbase];
            if ((unsigned)(xbase + 1) < (unsigned)WW) v.y = r0[xbase + 1] + r1[xbase + 1];
            if ((unsigned)(xbase + 2) < (unsigned)WW) v.z = r0[xbase + 2] + r1[xbase + 2];
            if ((unsigned)(xbase + 3) < (unsigned)WW) v.w = r0[xbase + 3] + r1[xbase + 3];
        }
    }

    ((float4*)out)[((size_t)b * NP + p) * (HW / 4) + idx] = v;
}

extern "C" void kernel_launch(void* const* d_in, const int* in_sizes, int n_in,
                              void* d_out, int out_size) {
    const float* in1 = (const float*)d_in[0];
    const float* in2 = (const float*)d_in[1];
    float* out = (float*)d_out;

    dim3 g1((BB * HW) / 128, 2, 1);
    dot_kernel<<<g1, 256>>>(in1, in2);

    dim3 g2(HW / (4 * 256) * 4 / 4, NP, BB);   // (9, 441, 8)
    gather_kernel<<<dim3(9, NP, BB), 256>>>(out);
}

// round 3
// speedup vs baseline: 1.1812x; 1.1812x over previous
#include <cuda_runtime.h>

#define BB 8
#define CC 256
#define HH 96
#define WW 96
#define HW (HH*WW)          // 9216
#define PATCH 21
#define NP    (PATCH*PATCH) // 441
#define HALFP 10
#define DILP 2

// D = sum_c in1*in2 : B*H*W floats = 1.18 MB (L2-resident between kernels)
__device__ float g_D[BB * HW];

// ---------------------------------------------------------------------------
// Kernel 1: channel dot product (R1 version — proven 32.5us).
// Block = 256 = 32 float4 lanes (128 spatial floats) x 8 groups of 32 ch.
// ---------------------------------------------------------------------------
__global__ void __launch_bounds__(256) dot_kernel(const float* __restrict__ a,
                                                  const float* __restrict__ b) {
    __shared__ float4 red[256];

    const int tid  = threadIdx.x;
    const int lane = tid & 31;
    const int cg   = tid >> 5;

    const int sbase = blockIdx.x * 128;
    const int bidx  = sbase / HW;
    const int hw    = (sbase % HW) + lane * 4;

    const float4* __restrict__ A =
        (const float4*)(a + (size_t)bidx * CC * HW + hw);
    const float4* __restrict__ Bp =
        (const float4*)(b + (size_t)bidx * CC * HW + hw);

    const int cstride = HW / 4;
    const int c0 = cg * 32;

    float4 acc = make_float4(0.f, 0.f, 0.f, 0.f);
    #pragma unroll 8
    for (int c = 0; c < 32; ++c) {
        const size_t off = (size_t)(c0 + c) * cstride;
        float4 x = A[off];
        float4 y = Bp[off];
        acc.x = fmaf(x.x, y.x, acc.x);
        acc.y = fmaf(x.y, y.y, acc.y);
        acc.z = fmaf(x.z, y.z, acc.z);
        acc.w = fmaf(x.w, y.w, acc.w);
    }

    red[tid] = acc;
    __syncthreads();

    if (tid < 32) {
        float4 r = red[tid];
        #pragma unroll
        for (int k = 1; k < 8; ++k) {
            float4 t = red[tid + 32 * k];
            r.x += t.x; r.y += t.y; r.z += t.z; r.w += t.w;
        }
        ((float4*)g_D)[(size_t)blockIdx.x * 32 + tid] = r;
    }
}

// ---------------------------------------------------------------------------
// Kernel 2: gather with smem tiling.
// Block = (y, b). Stage 21 source rows (even shifts, +-20 col halo) into a
// zero-padded smem tile, then stream out all 441*96 outputs for this (b,y).
// No bounds checks in the hot loop; source L2 traffic ~6MB total (was 130MB).
// ---------------------------------------------------------------------------
#define TROW 136                     // 96 + 2*20 halo
__global__ void __launch_bounds__(256) gather_kernel(float* __restrict__ out) {
    __shared__ float tile[PATCH * TROW];   // 21*136*4 = 11424 B

    const int tid = threadIdx.x;
    const int y   = blockIdx.x;            // 0..95
    const int b   = blockIdx.y;            // 0..7

    // Zero-fill (halo regions stay zero)
    #pragma unroll
    for (int i = tid; i < PATCH * TROW; i += 256) tile[i] = 0.f;
    __syncthreads();

    // Load the 21 candidate rows: row r holds D[b, y + (r-10)*2, :] at col+20.
    // 21 rows x 24 float4 = 504 float4 loads.
    const float4* __restrict__ D4 = (const float4*)g_D;
    for (int i = tid; i < PATCH * 24; i += 256) {
        const int r  = i / 24;
        const int x4 = i - r * 24;
        const int sy = y + (r - HALFP) * DILP;
        if ((unsigned)sy < (unsigned)HH) {
            float4 v = D4[(b * HH + sy) * 24 + x4];
            // dest col = 20 + x4*4, 16B-aligned since 20 % 4 == 0
            *(float4*)(tile + r * TROW + 20 + x4 * 4) = v;
        }
    }
    __syncthreads();

    // Emit: 441 offsets x 24 float4 per row = 10584 float4 stores.
    // item i -> p = i/24, x4 = i%24. smem col = px*2 + x4*4 (even, 8B-aligned).
    float4* __restrict__ O4 = (float4*)out;
    const size_t obase = ((size_t)b * NP) * (HW / 4) + y * 24;

    for (int i = tid; i < NP * 24; i += 256) {
        const int p  = i / 24;
        const int x4 = i - p * 24;
        const int py = p / PATCH;
        const int px = p - py * PATCH;

        const int addr = py * TROW + px * 2 + x4 * 4;   // even -> float2 ok
        const float2* sp = (const float2*)(tile + addr);
        float2 lo = sp[0];
        float2 hi = sp[1];

        O4[obase + (size_t)p * (HW / 4) + x4] =
            make_float4(lo.x, lo.y, hi.x, hi.y);
    }
}

extern "C" void kernel_launch(void* const* d_in, const int* in_sizes, int n_in,
                              void* d_out, int out_size) {
    const float* in1 = (const float*)d_in[0];
    const float* in2 = (const float*)d_in[1];
    float* out = (float*)d_out;

    dot_kernel<<<(BB * HW) / 128, 256>>>(in1, in2);
    gather_kernel<<<dim3(HH, BB), 256>>>(out);
}

// round 5
// speedup vs baseline: 1.1896x; 1.0071x over previous
#include <cuda_runtime.h>

#define BB 8
#define CC 256
#define HH 96
#define WW 96
#define HW (HH*WW)          // 9216
#define PATCH 21
#define NP    (PATCH*PATCH) // 441
#define HALFP 10
#define DILP 2
#define TROW 136            // 96 + 2*20 halo

#define NDOT  576           // dot units: 128 spatial floats x 256ch each
#define NGATH 768           // gather units: (b,y)
#define NPROD 288           // producer blocks
#define NCONS 304           // consumer blocks
#define GRID  (NPROD + NCONS)   // 592 = 148*4, all resident at occ 4

__device__ float g_D[BB * HW];     // 1.18 MB, L2-resident
__device__ int   g_cnt[BB];        // per-batch completed dot units (target 72)

__global__ void init_kernel() {
    if (threadIdx.x < BB) g_cnt[threadIdx.x] = 0;
}

__global__ void __launch_bounds__(256, 4) fused_kernel(
        const float* __restrict__ a,
        const float* __restrict__ b,
        float* __restrict__ out) {
    __shared__ union {
        float4 red[256];
        float  tile[PATCH * TROW];   // 11424 B
    } sm;

    const int tid = threadIdx.x;
    const int bid = blockIdx.x;

    if (bid < NPROD) {
        // ===================== PRODUCER: dot units =====================
        const int lane = tid & 31;
        const int cg   = tid >> 5;
        const int cstride = HW / 4;
        const int c0 = cg * 32;

        for (int u = bid; u < NDOT; u += NPROD) {
            const int sbase = u * 128;
            const int bidx  = u / 72;                  // batch
            const int hw    = (sbase % HW) + lane * 4;

            const float4* __restrict__ A =
                (const float4*)(a + (size_t)bidx * CC * HW + hw);
            const float4* __restrict__ Bp =
                (const float4*)(b + (size_t)bidx * CC * HW + hw);

            float4 acc = make_float4(0.f, 0.f, 0.f, 0.f);
            #pragma unroll 4
            for (int c = 0; c < 32; ++c) {
                const size_t off = (size_t)(c0 + c) * cstride;
                float4 x = A[off];
                float4 y = Bp[off];
                acc.x = fmaf(x.x, y.x, acc.x);
                acc.y = fmaf(x.y, y.y, acc.y);
                acc.z = fmaf(x.z, y.z, acc.z);
                acc.w = fmaf(x.w, y.w, acc.w);
            }

            sm.red[tid] = acc;
            __syncthreads();
            if (tid < 32) {
                float4 r = sm.red[tid];
                #pragma unroll
                for (int k = 1; k < 8; ++k) {
                    float4 t = sm.red[tid + 32 * k];
                    r.x += t.x; r.y += t.y; r.z += t.z; r.w += t.w;
                }
                ((float4*)g_D)[(size_t)u * 32 + tid] = r;
            }
            __syncthreads();                       // reduce done, smem free
            if (tid == 0) {
                __threadfence();                   // publish g_D
                atomicAdd(&g_cnt[bidx], 1);
            }
        }
    } else {
        // ===================== CONSUMER: gather units =====================
        const float4* __restrict__ D4 = (const float4*)g_D;
        float4* __restrict__ O4 = (float4*)out;

        for (int g = bid - NPROD; g < NGATH; g += NCONS) {
            const int bb = g / HH;                 // batch
            const int y  = g - bb * HH;

            // zero tile while (possibly) waiting
            for (int i = tid; i < PATCH * TROW; i += 256) sm.tile[i] = 0.f;

            if (tid == 0) {
                volatile int* c = &g_cnt[bb];
                while (*c < 72) __nanosleep(100);
                __threadfence();                   // acquire
            }
            __syncthreads();

            // stage 21 candidate rows (+-20 col halo pre-zeroed)
            for (int i = tid; i < PATCH * 24; i += 256) {
                const int r  = i / 24;
                const int x4 = i - r * 24;
                const int sy = y + (r - HALFP) * DILP;
                if ((unsigned)sy < (unsigned)HH) {
                    float4 v = D4[(bb * HH + sy) * 24 + x4];
                    *(float4*)(sm.tile + r * TROW + 20 + x4 * 4) = v;
                }
            }
            __syncthreads();

            // emit 441 x 24 float4 streaming stores
            const size_t obase = ((size_t)bb * NP) * (HW / 4) + y * 24;
            for (int i = tid; i < NP * 24; i += 256) {
                const int p  = i / 24;
                const int x4 = i - p * 24;
                const int py = p / PATCH;
                const int px = p - py * PATCH;

                const float2* sp =
                    (const float2*)(sm.tile + py * TROW + px * 2 + x4 * 4);
                float2 lo = sp[0];
                float2 hi = sp[1];

                O4[obase + (size_t)p * (HW / 4) + x4] =
                    make_float4(lo.x, lo.y, hi.x, hi.y);
            }
            __syncthreads();                       // tile reuse safety
        }
    }
}

extern "C" void kernel_launch(void* const* d_in, const int* in_sizes, int n_in,
                              void* d_out, int out_size) {
    const float* in1 = (const float*)d_in[0];
    const float* in2 = (const float*)d_in[1];
    float* out = (float*)d_out;

    init_kernel<<<1, 32>>>();
    fused_kernel<<<GRID, 256>>>(in1, in2, out);
}

// round 6
// speedup vs baseline: 1.1952x; 1.0048x over previous
#include <cuda_runtime.h>

#define BB 8
#define CC 256
#define HH 96
#define WW 96
#define HW (HH*WW)          // 9216
#define PATCH 21
#define NP    (PATCH*PATCH) // 441
#define HALFP 10
#define DILP 2
#define TROW 136            // 96 + 2*20 halo

#define NDOT  576           // dot units: 128 spatial floats x 256ch each
#define NGATH 768           // gather units: (b,y)
#define NPROD 288           // producer blocks
#define NCONS 304           // consumer blocks
#define GRID  (NPROD + NCONS)   // 592 = 148*4, all resident at occ 4

__device__ float g_D[BB * HW];     // 1.18 MB, L2-resident
__device__ int   g_cnt[BB];        // per-batch completed dot units (target 72)
__device__ int   g_done;           // finished consumer blocks (self-reset)

__global__ void __launch_bounds__(256, 4) fused_kernel(
        const float* __restrict__ a,
        const float* __restrict__ b,
        float* __restrict__ out) {
    __shared__ union {
        float4 red[256];
        float  tile[PATCH * TROW];   // 11424 B
    } sm;

    const int tid = threadIdx.x;
    const int bid = blockIdx.x;

    if (bid < NPROD) {
        // ===================== PRODUCER: dot units =====================
        const int lane = tid & 31;
        const int cg   = tid >> 5;
        const int cstride = HW / 4;
        const int c0 = cg * 32;

        for (int u = bid; u < NDOT; u += NPROD) {
            const int sbase = u * 128;
            const int bidx  = u / 72;                  // batch
            const int hw    = (sbase % HW) + lane * 4;

            const float4* __restrict__ A =
                (const float4*)(a + (size_t)bidx * CC * HW + hw);
            const float4* __restrict__ Bp =
                (const float4*)(b + (size_t)bidx * CC * HW + hw);

            float4 acc = make_float4(0.f, 0.f, 0.f, 0.f);
            #pragma unroll 4
            for (int c = 0; c < 32; ++c) {
                const size_t off = (size_t)(c0 + c) * cstride;
                float4 x = __ldcs(A + off);     // streaming: no L2 reuse
                float4 y = __ldcs(Bp + off);
                acc.x = fmaf(x.x, y.x, acc.x);
                acc.y = fmaf(x.y, y.y, acc.y);
                acc.z = fmaf(x.z, y.z, acc.z);
                acc.w = fmaf(x.w, y.w, acc.w);
            }

            sm.red[tid] = acc;
            __syncthreads();
            if (tid < 32) {
                float4 r = sm.red[tid];
                #pragma unroll
                for (int k = 1; k < 8; ++k) {
                    float4 t = sm.red[tid + 32 * k];
                    r.x += t.x; r.y += t.y; r.z += t.z; r.w += t.w;
                }
                ((float4*)g_D)[(size_t)u * 32 + tid] = r;
            }
            __syncthreads();                       // reduce done, smem free
            if (tid == 0) {
                __threadfence();                   // publish g_D
                atomicAdd(&g_cnt[bidx], 1);
            }
        }
    } else {
        // ===================== CONSUMER: gather units =====================
        const float4* __restrict__ D4 = (const float4*)g_D;
        float4* __restrict__ O4 = (float4*)out;

        for (int g = bid - NPROD; g < NGATH; g += NCONS) {
            const int bb = g / HH;                 // batch
            const int y  = g - bb * HH;

            // zero tile while (possibly) waiting
            for (int i = tid; i < PATCH * TROW; i += 256) sm.tile[i] = 0.f;

            if (tid == 0) {
                volatile int* c = &g_cnt[bb];
                while (*c < 72) __nanosleep(100);
                __threadfence();                   // acquire
            }
            __syncthreads();

            // stage 21 candidate rows (+-20 col halo pre-zeroed)
            for (int i = tid; i < PATCH * 24; i += 256) {
                const int r  = i / 24;
                const int x4 = i - r * 24;
                const int sy = y + (r - HALFP) * DILP;
                if ((unsigned)sy < (unsigned)HH) {
                    float4 v = D4[(bb * HH + sy) * 24 + x4];
                    *(float4*)(sm.tile + r * TROW + 20 + x4 * 4) = v;
                }
            }
            __syncthreads();

            // emit 441 x 24 float4 streaming stores
            const size_t obase = ((size_t)bb * NP) * (HW / 4) + y * 24;
            for (int i = tid; i < NP * 24; i += 256) {
                const int p  = i / 24;
                const int x4 = i - p * 24;
                const int py = p / PATCH;
                const int px = p - py * PATCH;

                const float2* sp =
                    (const float2*)(sm.tile + py * TROW + px * 2 + x4 * 4);
                float2 lo = sp[0];
                float2 hi = sp[1];

                __stcs(&O4[obase + (size_t)p * (HW / 4) + x4],
                       make_float4(lo.x, lo.y, hi.x, hi.y));
            }
            __syncthreads();                       // tile reuse safety
        }

        // ---- self-clean: last consumer block resets sync state for the
        // next graph replay (no separate init kernel needed). All g_cnt
        // readers are done (every consumer finished its waits before its
        // g_done increment), and producers have no pending increments.
        if (tid == 0) {
            __threadfence();
            int d = atomicAdd(&g_done, 1);
            if (d == NCONS - 1) {
                #pragma unroll
                for (int i = 0; i < BB; ++i) g_cnt[i] = 0;
                g_done = 0;
                __threadfence();
            }
        }
    }
}

extern "C" void kernel_launch(void* const* d_in, const int* in_sizes, int n_in,
                              void* d_out, int out_size) {
    const float* in1 = (const float*)d_in[0];
    const float* in2 = (const float*)d_in[1];
    float* out = (float*)d_out;

    fused_kernel<<<GRID, 256>>>(in1, in2, out);
}

// round 8
// speedup vs baseline: 1.1959x; 1.0006x over previous
#include <cuda_runtime.h>

#define BB 8
#define CC 256
#define HH 96
#define WW 96
#define HW (HH*WW)          // 9216
#define PATCH 21
#define NP    (PATCH*PATCH) // 441
#define HALFP 10
#define DILP 2
#define TROW 136            // 96 + 2*20 halo

#define NDOT  576           // dot units: 128 spatial floats x 256ch each
#define NGATH 768           // gather units: (b,y)
#define NPROD 288           // producer blocks
#define NCONS 304           // consumer blocks
#define GRID  (NPROD + NCONS)   // 592 = 148*4, all resident at occ 4

__device__ float g_D[BB * HW];     // 1.18 MB, L2-resident
__device__ int   g_cnt[BB];        // per-batch completed dot units (target 72)
__device__ int   g_done;           // finished consumer blocks (self-reset)

__global__ void __launch_bounds__(256, 4) fused_kernel(
        const float* __restrict__ a,
        const float* __restrict__ b,
        float* __restrict__ out) {
    __shared__ union {
        float4 red[256];
        float  tile[PATCH * TROW];   // 11424 B
    } sm;

    const int tid = threadIdx.x;
    const int bid = blockIdx.x;

    if (bid < NPROD) {
        // ===================== PRODUCER: dot units =====================
        const int lane = tid & 31;
        const int cg   = tid >> 5;
        const int cstride = HW / 4;
        const int c0 = cg * 32;

        for (int u = bid; u < NDOT; u += NPROD) {
            const int sbase = u * 128;
            const int bidx  = u / 72;                  // batch
            const int hw    = (sbase % HW) + lane * 4;

            const float4* __restrict__ A =
                (const float4*)(a + (size_t)bidx * CC * HW + hw);
            const float4* __restrict__ Bp =
                (const float4*)(b + (size_t)bidx * CC * HW + hw);

            float4 acc = make_float4(0.f, 0.f, 0.f, 0.f);
            #pragma unroll 4
            for (int c = 0; c < 32; ++c) {
                const size_t off = (size_t)(c0 + c) * cstride;
                float4 x = A[off];                 // plain loads (hints hurt)
                float4 y = Bp[off];
                acc.x = fmaf(x.x, y.x, acc.x);
                acc.y = fmaf(x.y, y.y, acc.y);
                acc.z = fmaf(x.z, y.z, acc.z);
                acc.w = fmaf(x.w, y.w, acc.w);
            }

            sm.red[tid] = acc;
            __syncthreads();
            if (tid < 32) {
                float4 r = sm.red[tid];
                #pragma unroll
                for (int k = 1; k < 8; ++k) {
                    float4 t = sm.red[tid + 32 * k];
                    r.x += t.x; r.y += t.y; r.z += t.z; r.w += t.w;
                }
                ((float4*)g_D)[(size_t)u * 32 + tid] = r;
            }
            __syncthreads();                       // reduce done, smem free
            if (tid == 0) {
                __threadfence();                   // publish g_D
                atomicAdd(&g_cnt[bidx], 1);
            }
        }
    } else {
        // ===================== CONSUMER: gather units =====================
        const float4* __restrict__ D4 = (const float4*)g_D;
        float4* __restrict__ O4 = (float4*)out;

        for (int g = bid - NPROD; g < NGATH; g += NCONS) {
            const int bb = g / HH;                 // batch
            const int y  = g - bb * HH;

            // zero tile while (possibly) waiting
            for (int i = tid; i < PATCH * TROW; i += 256) sm.tile[i] = 0.f;

            if (tid == 0) {
                volatile int* c = &g_cnt[bb];
                while (*c < 72) __nanosleep(100);
                __threadfence();                   // acquire
            }
            __syncthreads();

            // stage 21 candidate rows (+-20 col halo pre-zeroed)
            for (int i = tid; i < PATCH * 24; i += 256) {
                const int r  = i / 24;
                const int x4 = i - r * 24;
                const int sy = y + (r - HALFP) * DILP;
                if ((unsigned)sy < (unsigned)HH) {
                    float4 v = D4[(bb * HH + sy) * 24 + x4];
                    *(float4*)(sm.tile + r * TROW + 20 + x4 * 4) = v;
                }
            }
            __syncthreads();

            // emit 441 x 24 float4 stores (plain: streaming hints hurt)
            const size_t obase = ((size_t)bb * NP) * (HW / 4) + y * 24;
            for (int i = tid; i < NP * 24; i += 256) {
                const int p  = i / 24;
                const int x4 = i - p * 24;
                const int py = p / PATCH;
                const int px = p - py * PATCH;

                const float2* sp =
                    (const float2*)(sm.tile + py * TROW + px * 2 + x4 * 4);
                float2 lo = sp[0];
                float2 hi = sp[1];

                O4[obase + (size_t)p * (HW / 4) + x4] =
                    make_float4(lo.x, lo.y, hi.x, hi.y);
            }
            __syncthreads();                       // tile reuse safety
        }

        // ---- self-clean: last consumer block resets sync state for the
        // next graph replay (proven in R6). All g_cnt readers finished
        // before incrementing g_done; producer increments all observed.
        if (tid == 0) {
            __threadfence();
            int d = atomicAdd(&g_done, 1);
            if (d == NCONS - 1) {
                #pragma unroll
                for (int i = 0; i < BB; ++i) g_cnt[i] = 0;
                g_done = 0;
                __threadfence();
            }
        }
    }
}

extern "C" void kernel_launch(void* const* d_in, const int* in_sizes, int n_in,
                              void* d_out, int out_size) {
    const float* in1 = (const float*)d_in[0];
    const float* in2 = (const float*)d_in[1];
    float* out = (float*)d_out;

    fused_kernel<<<GRID, 256>>>(in1, in2, out);
}